// round 5
// baseline (speedup 1.0000x reference)
#include <cuda_runtime.h>
#include <cuda_bf16.h>

// MaskSupervisionLoss on GB300 (sm_103a) — single fused kernel, 3-way group split.
// Inputs: pred_attn f32 (32,8,256,256), gt_masks f32 (32,8,256,256), num_objects i32 (32)
// Output: scalar f32 loss.

#define NB    32
#define NSLOT 8
#define HW    65536
#define NCH   32
#define NGRP  3
#define NPOS2 1024                 // float2 per chunk per slot (2048 positions)
#define TPB   128
#define NIT   (NPOS2 / TPB)        // 8 iterations
#define NV    66
#define EPSF  1e-6f
#define BLOCKS_PER_BATCH (NCH * NGRP)   // 96

// canonical layout (per batch):
//  0 bg_inter, 1 bg_psum, 2 bg_gsum, 3..9 psum fg0-6, 10..16 gsum fg0-6,
//  17..65 inter[p][g] = 17 + 7p + g

__device__ float g_scratch[NB * NCH * NV];
__device__ float g_batch[NB * 3];
__device__ int   g_cnt[NB];        // zero-init; self-resetting
__device__ int   g_cnt_all;        // zero-init; self-resetting

// local-accumulator -> canonical index maps
__constant__ signed char c_map[NGRP][24] = {
    // G0: bg_inter, bg_psum, psum fg0, psum fg1, inter fg0 row, inter fg1 row
    { 0, 1, 3, 4, 17,18,19,20,21,22,23, 24,25,26,27,28,29,30, -1,-1,-1,-1,-1,-1 },
    // G1: psum fg2-4, inter rows fg2, fg3, fg4
    { 5, 6, 7, 31,32,33,34,35,36,37, 38,39,40,41,42,43,44, 45,46,47,48,49,50,51 },
    // G2: psum fg5-6, gsum slots 0..7 (bg_gsum + gsum fg0-6), inter rows fg5, fg6
    { 8, 9, 2, 10,11,12,13,14,15,16, 52,53,54,55,56,57,58, 59,60,61,62,63,64,65 }
};
__constant__ int c_nacc[NGRP] = { 18, 24, 24 };

// ---------------------------------------------------------------------------
// Per-group accumulation bodies. Double-buffered loads: next iteration's LDGs
// are issued before the current FMA tail (needs free registers -> 3-way split).
// ---------------------------------------------------------------------------

// G0: pred slots 0,1,2 ; gt slots 0..7 (11 float2 streams), 18 accumulators
__device__ __forceinline__ void body_g0(const float2* __restrict__ pr,
                                        const float2* __restrict__ gm,
                                        int tid, float* acc) {
    const int ss = HW / 2;
    float2 p[3], g[8], pn[3], gn[8];
#pragma unroll
    for (int s = 0; s < 3; s++) p[s] = pr[s * ss + tid];
#pragma unroll
    for (int s = 0; s < 8; s++) g[s] = gm[s * ss + tid];
#pragma unroll
    for (int k = 0; k < NIT; k++) {
        if (k < NIT - 1) {
            const int i = (k + 1) * TPB + tid;
#pragma unroll
            for (int s = 0; s < 3; s++) pn[s] = pr[s * ss + i];
#pragma unroll
            for (int s = 0; s < 8; s++) gn[s] = gm[s * ss + i];
        }
        // .x
        acc[0] = fmaf(p[0].x, g[0].x, acc[0]);
        acc[1] += p[0].x;
        acc[2] += p[1].x;
        acc[3] += p[2].x;
#pragma unroll
        for (int c = 0; c < 7; c++) acc[4  + c] = fmaf(p[1].x, g[c + 1].x, acc[4  + c]);
#pragma unroll
        for (int c = 0; c < 7; c++) acc[11 + c] = fmaf(p[2].x, g[c + 1].x, acc[11 + c]);
        // .y
        acc[0] = fmaf(p[0].y, g[0].y, acc[0]);
        acc[1] += p[0].y;
        acc[2] += p[1].y;
        acc[3] += p[2].y;
#pragma unroll
        for (int c = 0; c < 7; c++) acc[4  + c] = fmaf(p[1].y, g[c + 1].y, acc[4  + c]);
#pragma unroll
        for (int c = 0; c < 7; c++) acc[11 + c] = fmaf(p[2].y, g[c + 1].y, acc[11 + c]);
#pragma unroll
        for (int s = 0; s < 3; s++) p[s] = pn[s];
#pragma unroll
        for (int s = 0; s < 8; s++) g[s] = gn[s];
    }
}

// G1: pred slots 3,4,5 ; gt slots 1..7 (10 streams), 24 accumulators
__device__ __forceinline__ void body_g1(const float2* __restrict__ pr,
                                        const float2* __restrict__ gm,
                                        int tid, float* acc) {
    const int ss = HW / 2;
    float2 p[3], g[7], pn[3], gn[7];
#pragma unroll
    for (int s = 0; s < 3; s++) p[s] = pr[(s + 3) * ss + tid];
#pragma unroll
    for (int s = 0; s < 7; s++) g[s] = gm[(s + 1) * ss + tid];
#pragma unroll
    for (int k = 0; k < NIT; k++) {
        if (k < NIT - 1) {
            const int i = (k + 1) * TPB + tid;
#pragma unroll
            for (int s = 0; s < 3; s++) pn[s] = pr[(s + 3) * ss + i];
#pragma unroll
            for (int s = 0; s < 7; s++) gn[s] = gm[(s + 1) * ss + i];
        }
#pragma unroll
        for (int r = 0; r < 3; r++) acc[r] += p[r].x;
#pragma unroll
        for (int r = 0; r < 3; r++)
#pragma unroll
            for (int c = 0; c < 7; c++)
                acc[3 + r * 7 + c] = fmaf(p[r].x, g[c].x, acc[3 + r * 7 + c]);
#pragma unroll
        for (int r = 0; r < 3; r++) acc[r] += p[r].y;
#pragma unroll
        for (int r = 0; r < 3; r++)
#pragma unroll
            for (int c = 0; c < 7; c++)
                acc[3 + r * 7 + c] = fmaf(p[r].y, g[c].y, acc[3 + r * 7 + c]);
#pragma unroll
        for (int s = 0; s < 3; s++) p[s] = pn[s];
#pragma unroll
        for (int s = 0; s < 7; s++) g[s] = gn[s];
    }
}

// G2: pred slots 6,7 ; gt slots 0..7 (10 streams), 24 accumulators
// local acc: [0,1] psum fg5,fg6 ; [2..9] gsum slots 0..7 ; [10..23] inter rows
__device__ __forceinline__ void body_g2(const float2* __restrict__ pr,
                                        const float2* __restrict__ gm,
                                        int tid, float* acc) {
    const int ss = HW / 2;
    float2 p[2], g[8], pn[2], gn[8];
#pragma unroll
    for (int s = 0; s < 2; s++) p[s] = pr[(s + 6) * ss + tid];
#pragma unroll
    for (int s = 0; s < 8; s++) g[s] = gm[s * ss + tid];
#pragma unroll
    for (int k = 0; k < NIT; k++) {
        if (k < NIT - 1) {
            const int i = (k + 1) * TPB + tid;
#pragma unroll
            for (int s = 0; s < 2; s++) pn[s] = pr[(s + 6) * ss + i];
#pragma unroll
            for (int s = 0; s < 8; s++) gn[s] = gm[s * ss + i];
        }
        acc[0] += p[0].x;
        acc[1] += p[1].x;
#pragma unroll
        for (int s = 0; s < 8; s++) acc[2 + s] += g[s].x;
#pragma unroll
        for (int r = 0; r < 2; r++)
#pragma unroll
            for (int c = 0; c < 7; c++)
                acc[10 + r * 7 + c] = fmaf(p[r].x, g[c + 1].x, acc[10 + r * 7 + c]);
        acc[0] += p[0].y;
        acc[1] += p[1].y;
#pragma unroll
        for (int s = 0; s < 8; s++) acc[2 + s] += g[s].y;
#pragma unroll
        for (int r = 0; r < 2; r++)
#pragma unroll
            for (int c = 0; c < 7; c++)
                acc[10 + r * 7 + c] = fmaf(p[r].y, g[c + 1].y, acc[10 + r * 7 + c]);
#pragma unroll
        for (int s = 0; s < 2; s++) p[s] = pn[s];
#pragma unroll
        for (int s = 0; s < 8; s++) g[s] = gn[s];
    }
}

// ---------------------------------------------------------------------------
__global__ __launch_bounds__(TPB, 6)
void k_fused(const float* __restrict__ pred, const float* __restrict__ gt,
             const int* __restrict__ nobj, float* __restrict__ out) {
    const int grp   = blockIdx.x % NGRP;       // group fastest -> L2 reuse of gt
    const int chunk = blockIdx.x / NGRP;
    const int b     = blockIdx.y;
    const int tid   = threadIdx.x;
    const int wid   = tid >> 5;
    const int lane  = tid & 31;

    const size_t base = (size_t)b * NSLOT * (HW / 2) + (size_t)chunk * NPOS2;
    const float2* __restrict__ pr = (const float2*)pred + base;
    const float2* __restrict__ gm = (const float2*)gt   + base;

    float acc[24];
#pragma unroll
    for (int v = 0; v < 24; v++) acc[v] = 0.f;

    if (grp == 0)      body_g0(pr, gm, tid, acc);
    else if (grp == 1) body_g1(pr, gm, tid, acc);
    else               body_g2(pr, gm, tid, acc);

    const int nacc = c_nacc[grp];

    // warp tree-reduce, combine 4 warps via smem, publish canonical subset
    __shared__ float sw[4][24];
    __shared__ int   sflag;
#pragma unroll
    for (int v = 0; v < 24; v++) {
        float x = acc[v];
#pragma unroll
        for (int o = 16; o > 0; o >>= 1) x += __shfl_down_sync(0xffffffffu, x, o);
        if (lane == 0) sw[wid][v] = x;
    }
    __syncthreads();

    if (tid < nacc) {
        const float s = sw[0][tid] + sw[1][tid] + sw[2][tid] + sw[3][tid];
        g_scratch[(b * NCH + chunk) * NV + (int)c_map[grp][tid]] = s;
        __threadfence();
    }
    __syncthreads();

    if (tid == 0) sflag = (atomicAdd(&g_cnt[b], 1) == BLOCKS_PER_BATCH - 1);
    __syncthreads();
    if (!sflag) return;

    // ================= batch finisher (last block of this batch) =============
    __shared__ float part[132];
    __shared__ float sm66[NV];
    __shared__ float dice[49];
    __shared__ float dpt[128];

    __threadfence();
    for (int e = tid; e < 132; e += TPB) {
        const int v = e >> 1, h = e & 1;
        float s = 0.f;
#pragma unroll
        for (int c = 0; c < NCH / 2; c++)
            s += __ldcg(&g_scratch[(b * NCH + h * (NCH / 2) + c) * NV + v]);
        part[e] = s;
    }
    __syncthreads();
    if (tid < NV) sm66[tid] = part[2 * tid] + part[2 * tid + 1];
    __syncthreads();
    if (tid < 49) {
        const int p = tid / 7, g = tid % 7;
        dice[tid] = (2.f * sm66[17 + tid] + EPSF) / (sm66[3 + p] + sm66[10 + g] + EPSF);
    }
    __syncthreads();

    if (wid == 0) {
        int n = nobj[b];
        n = (n > 7) ? 7 : (n < 0 ? 0 : n);
#pragma unroll
        for (int k = 0; k < 4; k++) dpt[k * 32 + lane] = -1e30f;
        __syncwarp();
        if (lane == 0) dpt[0] = 0.f;
        __syncwarp();
        // layered bitmask DP: optimal assignment value == Hungarian optimum
#pragma unroll
        for (int L = 1; L <= 7; L++) {
            const int g = L - 1;
            if (g < n) {
#pragma unroll
                for (int k = 0; k < 4; k++) {
                    const int m = k * 32 + lane;
                    if (__popc(m) == L) {
                        float best = -1e30f;
#pragma unroll
                        for (int p = 0; p < 7; p++)
                            if (m & (1 << p))
                                best = fmaxf(best, dpt[m ^ (1 << p)] + dice[p * 7 + g]);
                        dpt[m] = best;
                    }
                }
            }
            __syncwarp();
        }
        float best = -1e30f;
        if (n > 0) {
#pragma unroll
            for (int k = 0; k < 4; k++) {
                const int m = k * 32 + lane;
                if (__popc(m) == n) best = fmaxf(best, dpt[m]);
            }
        }
#pragma unroll
        for (int o = 16; o > 0; o >>= 1)
            best = fmaxf(best, __shfl_xor_sync(0xffffffffu, best, o));
        if (lane == 0) {
            g_batch[b * 3 + 0] = (2.f * sm66[0] + EPSF) / (sm66[1] + sm66[2] + EPSF);
            g_batch[b * 3 + 1] = (float)n;
            g_batch[b * 3 + 2] = (n > 0) ? best : 0.f;
        }
    }
    __syncthreads();

    if (tid == 0) {
        g_cnt[b] = 0;                       // reset for next graph replay
        __threadfence();
        sflag = (atomicAdd(&g_cnt_all, 1) == NB - 1);
    }
    __syncthreads();
    if (!sflag) return;

    // ================= global finisher =================
    if (wid == 0) {
        __threadfence();
        const float bgd = __ldcg(&g_batch[lane * 3 + 0]);
        const float nn  = __ldcg(&g_batch[lane * 3 + 1]);
        const float sv  = __ldcg(&g_batch[lane * 3 + 2]);
        float bg  = 1.f - bgd;
        float tot = nn;
        float ss  = (nn > 0.f) ? sv : 0.f;
#pragma unroll
        for (int o = 16; o > 0; o >>= 1) {
            bg  += __shfl_xor_sync(0xffffffffu, bg,  o);
            tot += __shfl_xor_sync(0xffffffffu, tot, o);
            ss  += __shfl_xor_sync(0xffffffffu, ss,  o);
        }
        if (lane == 0) {
            const float fg = (tot > 0.f) ? (tot - ss) / tot : 0.f;
            out[0] = bg * (1.f / (float)NB) + fg;
            g_cnt_all = 0;                  // reset for next graph replay
        }
    }
}

// ---------------------------------------------------------------------------
extern "C" void kernel_launch(void* const* d_in, const int* in_sizes, int n_in,
                              void* d_out, int out_size) {
    const float* pred = (const float*)d_in[0];
    const float* gt   = (const float*)d_in[1];
    const int*   nobj = (const int*)d_in[2];
    float*       out  = (float*)d_out;

    dim3 grid(NCH * NGRP, NB);
    k_fused<<<grid, TPB>>>(pred, gt, nobj, out);
}

// round 7
// speedup vs baseline: 1.2740x; 1.2740x over previous
#include <cuda_runtime.h>
#include <cuda_bf16.h>
#include <cstdint>

// MaskSupervisionLoss on GB300 (sm_103a) — fused kernel with cp.async smem pipeline.
// Inputs: pred_attn f32 (32,8,256,256), gt_masks f32 (32,8,256,256), num_objects i32 (32)
// Output: scalar f32 loss.

#define NB     32
#define NSLOT  8
#define HW     65536
#define NCH    64
#define CPOS   1024                // positions per chunk
#define TILE   256                 // positions per tile
#define NTILE  (CPOS / TILE)       // 4
#define TPB    128
#define NV     66
#define EPSF   1e-6f
#define NSTRM  16                  // 8 pred + 8 gt streams

// canonical layout (per batch):
//  0 bg_inter, 1 bg_psum, 2 bg_gsum, 3..9 psum fg0-6, 10..16 gsum fg0-6,
//  17..65 inter[p][g] = 17 + 7p + g

__device__ float g_scratch[NB * NCH * NV];
__device__ float g_batch[NB * 3];
__device__ int   g_cnt[NB];        // zero-init; self-resetting
__device__ int   g_cnt_all;        // zero-init; self-resetting

__device__ __forceinline__ void cp16(unsigned int dst_smem, const float* src) {
    asm volatile("cp.async.cg.shared.global [%0], [%1], 16;\n"
                 :: "r"(dst_smem), "l"(src));
}
__device__ __forceinline__ void cp_commit() {
    asm volatile("cp.async.commit_group;\n");
}
template <int N>
__device__ __forceinline__ void cp_wait() {
    asm volatile("cp.async.wait_group %0;\n" :: "n"(N));
}

// ---------------------------------------------------------------------------
__global__ __launch_bounds__(TPB, 4)
void k_fused(const float* __restrict__ pred, const float* __restrict__ gt,
             const int* __restrict__ nobj, float* __restrict__ out) {
    const int chunk = blockIdx.x;
    const int b     = blockIdx.y;
    const int tid   = threadIdx.x;
    const int wid   = tid >> 5;
    const int lane  = tid & 31;

    // double-buffered tile: [stage][stream][TILE floats]
    __shared__ float buf[2][NSTRM][TILE];
    __shared__ float sw[4][NV];
    __shared__ int   sflag;

    const float* __restrict__ bp = pred + (size_t)b * NSLOT * HW + chunk * CPOS;
    const float* __restrict__ bg = gt   + (size_t)b * NSLOT * HW + chunk * CPOS;

    // per-thread cp.async mapping: 8 ops of 16B per tile
    //   op o = k*TPB + tid ; stream s = o/64 ; 16B-unit offset w = o%64
    const unsigned int smem_base =
        (unsigned int)__cvta_generic_to_shared(&buf[0][0][0]);

    float acc[NV];
#pragma unroll
    for (int v = 0; v < NV; v++) acc[v] = 0.f;

    // ---- prologue: prefetch tile 0 into stage 0
    {
#pragma unroll
        for (int k = 0; k < 8; k++) {
            const int o = k * TPB + tid;
            const int s = o >> 6;
            const int w = o & 63;
            const float* src = ((s < 8) ? (bp + s * HW) : (bg + (s - 8) * HW)) + w * 4;
            cp16(smem_base + (unsigned int)((s * TILE + w * 4) * 4), src);
        }
        cp_commit();
    }

    // ---- pipelined main loop
#pragma unroll
    for (int t = 0; t < NTILE; t++) {
        const int st = t & 1;
        if (t < NTILE - 1) {
            const int nst  = (t + 1) & 1;
            const int goff = (t + 1) * TILE;
#pragma unroll
            for (int k = 0; k < 8; k++) {
                const int o = k * TPB + tid;
                const int s = o >> 6;
                const int w = o & 63;
                const float* src = ((s < 8) ? (bp + s * HW) : (bg + (s - 8) * HW)) + goff + w * 4;
                cp16(smem_base + (unsigned int)(((nst * NSTRM + s) * TILE + w * 4) * 4), src);
            }
            cp_commit();
            cp_wait<1>();          // tile t arrived; t+1 may still be in flight
        } else {
            cp_wait<0>();
        }
        __syncthreads();

        // compute: thread handles positions 2*tid, 2*tid+1 of this tile
        float2 p[8], g[8];
#pragma unroll
        for (int s = 0; s < 8; s++)
            p[s] = ((const float2*)&buf[st][s][0])[tid];
#pragma unroll
        for (int s = 0; s < 8; s++)
            g[s] = ((const float2*)&buf[st][8 + s][0])[tid];

        // .x
        acc[0] = fmaf(p[0].x, g[0].x, acc[0]);
        acc[1] += p[0].x;
        acc[2] += g[0].x;
#pragma unroll
        for (int r = 0; r < 7; r++) acc[3 + r]  += p[r + 1].x;
#pragma unroll
        for (int c = 0; c < 7; c++) acc[10 + c] += g[c + 1].x;
#pragma unroll
        for (int r = 0; r < 7; r++)
#pragma unroll
            for (int c = 0; c < 7; c++)
                acc[17 + r * 7 + c] = fmaf(p[r + 1].x, g[c + 1].x, acc[17 + r * 7 + c]);
        // .y
        acc[0] = fmaf(p[0].y, g[0].y, acc[0]);
        acc[1] += p[0].y;
        acc[2] += g[0].y;
#pragma unroll
        for (int r = 0; r < 7; r++) acc[3 + r]  += p[r + 1].y;
#pragma unroll
        for (int c = 0; c < 7; c++) acc[10 + c] += g[c + 1].y;
#pragma unroll
        for (int r = 0; r < 7; r++)
#pragma unroll
            for (int c = 0; c < 7; c++)
                acc[17 + r * 7 + c] = fmaf(p[r + 1].y, g[c + 1].y, acc[17 + r * 7 + c]);

        __syncthreads();           // all warps done reading before buffer reuse
    }

    // ---- block reduction: warp tree + 4-warp combine, publish canonical 66
#pragma unroll
    for (int v = 0; v < NV; v++) {
        float x = acc[v];
#pragma unroll
        for (int o = 16; o > 0; o >>= 1) x += __shfl_down_sync(0xffffffffu, x, o);
        if (lane == 0) sw[wid][v] = x;
    }
    __syncthreads();

    if (tid < NV) {
        g_scratch[(b * NCH + chunk) * NV + tid] =
            sw[0][tid] + sw[1][tid] + sw[2][tid] + sw[3][tid];
        __threadfence();
    }
    __syncthreads();

    if (tid == 0) sflag = (atomicAdd(&g_cnt[b], 1) == NCH - 1);
    __syncthreads();
    if (!sflag) return;

    // ================= batch finisher (last block of this batch) =============
    __shared__ float part[132];
    __shared__ float sm66[NV];
    __shared__ float dice[49];
    __shared__ float dpt[128];

    __threadfence();
    for (int e = tid; e < 132; e += TPB) {
        const int v = e >> 1, h = e & 1;
        float s = 0.f;
#pragma unroll
        for (int c = 0; c < NCH / 2; c++)
            s += __ldcg(&g_scratch[(b * NCH + h * (NCH / 2) + c) * NV + v]);
        part[e] = s;
    }
    __syncthreads();
    if (tid < NV) sm66[tid] = part[2 * tid] + part[2 * tid + 1];
    __syncthreads();
    if (tid < 49) {
        const int p = tid / 7, g = tid % 7;
        dice[tid] = (2.f * sm66[17 + tid] + EPSF) / (sm66[3 + p] + sm66[10 + g] + EPSF);
    }
    __syncthreads();

    if (wid == 0) {
        int n = nobj[b];
        n = (n > 7) ? 7 : (n < 0 ? 0 : n);
#pragma unroll
        for (int k = 0; k < 4; k++) dpt[k * 32 + lane] = -1e30f;
        __syncwarp();
        if (lane == 0) dpt[0] = 0.f;
        __syncwarp();
        // layered bitmask DP: optimal assignment value == Hungarian optimum
#pragma unroll
        for (int L = 1; L <= 7; L++) {
            const int g = L - 1;
            if (g < n) {
#pragma unroll
                for (int k = 0; k < 4; k++) {
                    const int m = k * 32 + lane;
                    if (__popc(m) == L) {
                        float best = -1e30f;
#pragma unroll
                        for (int p = 0; p < 7; p++)
                            if (m & (1 << p))
                                best = fmaxf(best, dpt[m ^ (1 << p)] + dice[p * 7 + g]);
                        dpt[m] = best;
                    }
                }
            }
            __syncwarp();
        }
        float best = -1e30f;
        if (n > 0) {
#pragma unroll
            for (int k = 0; k < 4; k++) {
                const int m = k * 32 + lane;
                if (__popc(m) == n) best = fmaxf(best, dpt[m]);
            }
        }
#pragma unroll
        for (int o = 16; o > 0; o >>= 1)
            best = fmaxf(best, __shfl_xor_sync(0xffffffffu, best, o));
        if (lane == 0) {
            g_batch[b * 3 + 0] = (2.f * sm66[0] + EPSF) / (sm66[1] + sm66[2] + EPSF);
            g_batch[b * 3 + 1] = (float)n;
            g_batch[b * 3 + 2] = (n > 0) ? best : 0.f;
        }
    }
    __syncthreads();

    if (tid == 0) {
        g_cnt[b] = 0;                       // reset for next graph replay
        __threadfence();
        sflag = (atomicAdd(&g_cnt_all, 1) == NB - 1);
    }
    __syncthreads();
    if (!sflag) return;

    // ================= global finisher =================
    if (wid == 0) {
        __threadfence();
        const float bgd = __ldcg(&g_batch[lane * 3 + 0]);
        const float nn  = __ldcg(&g_batch[lane * 3 + 1]);
        const float sv  = __ldcg(&g_batch[lane * 3 + 2]);
        float bg  = 1.f - bgd;
        float tot = nn;
        float ss  = (nn > 0.f) ? sv : 0.f;
#pragma unroll
        for (int o = 16; o > 0; o >>= 1) {
            bg  += __shfl_xor_sync(0xffffffffu, bg,  o);
            tot += __shfl_xor_sync(0xffffffffu, tot, o);
            ss  += __shfl_xor_sync(0xffffffffu, ss,  o);
        }
        if (lane == 0) {
            const float fg = (tot > 0.f) ? (tot - ss) / tot : 0.f;
            out[0] = bg * (1.f / (float)NB) + fg;
            g_cnt_all = 0;                  // reset for next graph replay
        }
    }
}

// ---------------------------------------------------------------------------
extern "C" void kernel_launch(void* const* d_in, const int* in_sizes, int n_in,
                              void* d_out, int out_size) {
    const float* pred = (const float*)d_in[0];
    const float* gt   = (const float*)d_in[1];
    const int*   nobj = (const int*)d_in[2];
    float*       out  = (float*)d_out;

    dim3 grid(NCH, NB);
    k_fused<<<grid, TPB>>>(pred, gt, nobj, out);
}